// round 16
// baseline (speedup 1.0000x reference)
#include <cuda_runtime.h>
#include <cuda_fp16.h>
#include <math.h>
#include <stdint.h>

#define BBATCH 2
#define SSEQ 2048
#define EEMB 1024
#define HHEADS 16
#define DKK 64
#define BHS (BBATCH*HHEADS*SSEQ)

// Scratch (all fp16, fragment-interleaved for single-LDS.128 operand fetch)
__device__ unsigned short g_xi[4096*1024];    // x: [m>>7][k>>6][(g*4+ks)32][lane32][comp4] b32 words
__device__ unsigned short g_wi[3][1024*1024]; // W: [n>>7][k>>6][(ng*2+sp)32][lane32][comp4]
__device__ unsigned short g_k[BHS*DKK];       // K: [bh][tile64][(ng*2+sp)16][lane32][comp4]
__device__ unsigned short g_v[BHS*DKK];       // V: [bh][tile64][(dn*2+kcp)16][lane32][comp4]
__device__ unsigned short g_q[BHS*DKK];       // Q: natural [bh][s][d]  (carries 0.125*log2e)

// ---------------- helpers ----------------
__device__ __forceinline__ void mma16(float* d, uint32_t a0, uint32_t a1,
                                      uint32_t a2, uint32_t a3,
                                      uint32_t b0, uint32_t b1)
{
    asm volatile("mma.sync.aligned.m16n8k16.row.col.f32.f16.f16.f32 "
        "{%0,%1,%2,%3}, {%4,%5,%6,%7}, {%8,%9}, {%0,%1,%2,%3};"
        : "+f"(d[0]), "+f"(d[1]), "+f"(d[2]), "+f"(d[3])
        : "r"(a0), "r"(a1), "r"(a2), "r"(a3), "r"(b0), "r"(b1));
}
__device__ __forceinline__ void mma16v(float* d, const uint4& a, uint32_t b0, uint32_t b1){
    mma16(d, a.x, a.y, a.z, a.w, b0, b1);
}
// fp16-accumulator mma: D packed half2: d0=(c0,c1) row gid, d1=(c2,c3) row gid+8
__device__ __forceinline__ void mma16h(uint32_t* d, const uint4& a, uint32_t b0, uint32_t b1)
{
    asm volatile("mma.sync.aligned.m16n8k16.row.col.f16.f16.f16.f16 "
        "{%0,%1}, {%2,%3,%4,%5}, {%6,%7}, {%0,%1};"
        : "+r"(d[0]), "+r"(d[1])
        : "r"(a.x), "r"(a.y), "r"(a.z), "r"(a.w), "r"(b0), "r"(b1));
}
__device__ __forceinline__ uint32_t ex2h2(uint32_t x){
    uint32_t r; asm("ex2.approx.f16x2 %0, %1;" : "=r"(r) : "r"(x)); return r;
}
__device__ __forceinline__ uint32_t packh2(float a, float b){
    __half2 h = __floats2half2_rn(a, b);
    return *(uint32_t*)&h;
}
__device__ __forceinline__ uint32_t smem_u32(const void* p){
    uint32_t a;
    asm("{ .reg .u64 t; cvta.to.shared.u64 t, %1; cvt.u32.u64 %0, t; }" : "=r"(a) : "l"(p));
    return a;
}

#define MBAR_INIT(a, c) asm volatile("mbarrier.init.shared.b64 [%0], %1;" :: "r"(a), "r"(c) : "memory")
#define MBAR_EXPECT(a, bytes) \
    asm volatile("mbarrier.arrive.expect_tx.shared.b64 _, [%0], %1;" :: "r"(a), "r"(bytes) : "memory")
#define BULK_G2S(dst, src, bytes, mbar) \
    asm volatile("cp.async.bulk.shared::cta.global.mbarrier::complete_tx::bytes [%0], [%1], %2, [%3];" \
        :: "r"(dst), "l"(src), "r"(bytes), "r"(mbar) : "memory")

#define MBAR_WAIT(mbar, par) do {                                            \
    uint32_t _m = (mbar); uint32_t _p = (par); uint32_t _done;               \
    asm volatile("{ .reg .pred p; mbarrier.try_wait.parity.acquire.cta.shared::cta.b64 p, [%1], %2; selp.b32 %0,1,0,p; }" \
        : "=r"(_done) : "r"(_m), "r"(_p) : "memory");                        \
    if (!_done) {                                                            \
        asm volatile("{ .reg .pred P1; WL%=: mbarrier.try_wait.parity.acquire.cta.shared::cta.b64 P1, [%0], %1, 0x989680; @P1 bra.uni WD%=; bra.uni WL%=; WD%=: }" \
            :: "r"(_m), "r"(_p) : "memory");                                 \
    }                                                                        \
} while(0)

// =====================================================================
// Prep (DEST-MAJOR, unchanged from R14)
// =====================================================================
__global__ __launch_bounds__(256)
void prep_kernel(const float* __restrict__ x, const float* __restrict__ Wk,
                 const float* __restrict__ Wv, const float* __restrict__ Wq)
{
    const int t = blockIdx.x * 256 + threadIdx.x;
    if (blockIdx.y == 0) {
        int l5 = t & 31, gid = l5 >> 2, tig = l5 & 3;
        int blk = t >> 5;
        int g = (blk & 31) >> 2, ks = blk & 3;
        int rbch = blk >> 5, ch = rbch & 15, rb = rbch >> 4;
        int mb = rb * 128 + g * 16 + gid;
        int kb = ch * 64 + ks * 16 + tig * 2;
        const float* xr0 = x + (size_t)mb * EEMB + kb;
        const float* xr8 = xr0 + 8 * EEMB;
        float2 a0 = *(const float2*)(xr0);
        float2 a1 = *(const float2*)(xr8);
        float2 a2 = *(const float2*)(xr0 + 8);
        float2 a3 = *(const float2*)(xr8 + 8);
        uint4 w;
        w.x = packh2(a0.x, a0.y);
        w.y = packh2(a1.x, a1.y);
        w.z = packh2(a2.x, a2.y);
        w.w = packh2(a3.x, a3.y);
        *(uint4*)((uint32_t*)g_xi + (size_t)t * 4) = w;
    } else {
        if (t >= 131072) return;
        const float* W = (blockIdx.y == 1) ? Wk : (blockIdx.y == 2) ? Wv : Wq;
        unsigned short* dst = g_wi[blockIdx.y - 1];
        int l5 = t & 31, gid = l5 >> 2, tig = l5 & 3;
        int blk = t >> 5;
        int ng = (blk & 31) >> 1, sp = blk & 1;
        int nbch = blk >> 5, ch = nbch & 15, nb = nbch >> 4;
        int n = nb * 128 + ng * 8 + gid;
        int kbase = ch * 64 + sp * 32 + tig * 2;
        const float* wr = W + (size_t)n * EEMB + kbase;
        float2 b0 = *(const float2*)(wr);
        float2 b1 = *(const float2*)(wr + 8);
        float2 b2 = *(const float2*)(wr + 16);
        float2 b3 = *(const float2*)(wr + 24);
        uint4 w;
        w.x = packh2(b0.x, b0.y);
        w.y = packh2(b1.x, b1.y);
        w.z = packh2(b2.x, b2.y);
        w.w = packh2(b3.x, b3.y);
        *(uint4*)((uint32_t*)dst + (size_t)t * 4) = w;
    }
}

// =====================================================================
// Merged projection (unchanged from R14)
// =====================================================================
#define PJ_SMEM (98304 + 32)

__global__ __launch_bounds__(256, 2)
void proj_mma(const float* __restrict__ theta)
{
    extern __shared__ char smc[];
    const uint32_t sb = smem_u32(smc);
    const uint32_t mb0 = sb + 98304;
    const int tid = threadIdx.x;
    const int wid = tid >> 5, lane = tid & 31;
    const int gid = lane >> 2, tig = lane & 3;
    const int wm = wid >> 1, wn = wid & 1;
    const int row0 = blockIdx.y * 128;
    const int col0g = blockIdx.x * 128;
    const int mode = col0g >> 10;
    const int coll = col0g & 1023;
    const int nb = coll >> 7;

    float acc[2][8][4];
    #pragma unroll
    for (int i = 0; i < 2; i++)
        #pragma unroll
        for (int j = 0; j < 8; j++)
            #pragma unroll
            for (int e = 0; e < 4; e++) acc[i][j][e] = 0.f;

    const unsigned short* Ab = g_xi + (size_t)blockIdx.y * 131072;
    const unsigned short* Wb = g_wi[mode] + (size_t)nb * 131072;

    auto issue = [&](int ch, int b) {
        uint32_t mbar = mb0 + b * 8;
        MBAR_EXPECT(mbar, 32768u);
        BULK_G2S(sb + b * 16384,         (const void*)(Ab + ch * 8192), 16384u, mbar);
        BULK_G2S(sb + 49152 + b * 16384, (const void*)(Wb + ch * 8192), 16384u, mbar);
    };

    if (tid == 0) { MBAR_INIT(mb0, 1); MBAR_INIT(mb0 + 8, 1); MBAR_INIT(mb0 + 16, 1); }
    __syncthreads();
    if (tid == 0) { issue(0, 0); issue(1, 1); }

    int buf = 0, par = 0;
    #pragma unroll 1
    for (int ch = 0; ch < 16; ch++) {
        MBAR_WAIT(mb0 + buf * 8, par);
        __syncthreads();
        if (ch + 2 < 16 && tid == 0) {
            int nbuf = buf + 2; if (nbuf >= 3) nbuf -= 3;
            issue(ch + 2, nbuf);
        }

        const uint4* As = (const uint4*)(smc + buf * 16384);
        const uint4* Ws = (const uint4*)(smc + 49152 + buf * 16384);
        #pragma unroll
        for (int sp = 0; sp < 2; sp++) {
            uint4 af[2][2];
            #pragma unroll
            for (int tm = 0; tm < 2; tm++)
                #pragma unroll
                for (int kso = 0; kso < 2; kso++)
                    af[tm][kso] = As[((2*wm+tm)*4 + 2*sp+kso) * 32 + lane];
            #pragma unroll
            for (int tn = 0; tn < 8; tn++) {
                uint4 wb = Ws[((wn*8+tn)*2 + sp) * 32 + lane];
                #pragma unroll
                for (int tm = 0; tm < 2; tm++) {
                    mma16v(acc[tm][tn], af[tm][0], wb.x, wb.y);
                    mma16v(acc[tm][tn], af[tm][1], wb.z, wb.w);
                }
            }
        }
        if (++buf == 3) { buf = 0; par ^= 1; }
    }

    // ---- epilogue ----
    #pragma unroll
    for (int tm = 0; tm < 2; tm++) {
        #pragma unroll
        for (int tn = 0; tn < 8; tn++) {
            #pragma unroll
            for (int half = 0; half < 2; half++) {
                int m = row0 + wm * 32 + tm * 16 + gid + half * 8;
                int nn = coll + wn * 64 + tn * 8 + 2 * tig;
                int b = m >> 11, s = m & (SSEQ - 1);
                int h = nn >> 6, d = nn & (DKK - 1);
                int bh = b * HHEADS + h;
                float v0 = acc[tm][tn][2 * half];
                float v1 = acc[tm][tn][2 * half + 1];
                if (mode == 0) {
                    int tile = s >> 6, key = s & 63;
                    int ng = key >> 3, gidk = key & 7;
                    int ks = d >> 4, sp = ks >> 1, kso = ks & 1;
                    int k16 = d & 15, khalf = k16 >> 3, tigk = (k16 & 7) >> 1;
                    int word = ((ng * 2 + sp) * 32 + gidk * 4 + tigk) * 4 + (kso * 2 + khalf);
                    uint32_t* dst32 = (uint32_t*)g_k;
                    dst32[(size_t)(bh * 32 + tile) * 2048 + word] = packh2(v0, v1);
                } else if (mode == 1) {
                    float pv0 = __shfl_xor_sync(0xffffffffu, v0, 4);
                    float pv1 = __shfl_xor_sync(0xffffffffu, v1, 4);
                    if (!(gid & 1)) {
                        int tile = s >> 6, key = s & 63;
                        int kc = key >> 4, kcp = kc >> 1, kco = kc & 1;
                        int key16 = key & 15, khalf = key16 >> 3, tigv = (key16 & 7) >> 1;
                        uint32_t* dst32 = (uint32_t*)g_v;
                        size_t base = (size_t)(bh * 32 + tile) * 2048;
                        int dn0 = d >> 3, gid0 = d & 7;
                        int w0 = ((dn0 * 2 + kcp) * 32 + gid0 * 4 + tigv) * 4 + (kco * 2 + khalf);
                        int d1 = d + 1, dn1 = d1 >> 3, gid1 = d1 & 7;
                        int w1 = ((dn1 * 2 + kcp) * 32 + gid1 * 4 + tigv) * 4 + (kco * 2 + khalf);
                        dst32[base + w0] = packh2(v0, pv0);
                        dst32[base + w1] = packh2(v1, pv1);
                    }
                } else {
                    float q0 = __cosf(v0 + __ldg(&theta[d]))     * 0.18033688011112042f;
                    float q1 = __cosf(v1 + __ldg(&theta[d + 1])) * 0.18033688011112042f;
                    uint32_t* dst32 = (uint32_t*)g_q;
                    dst32[(((size_t)bh * SSEQ + s) * DKK + d) >> 1] = packh2(q0, q1);
                }
            }
        }
    }
}

// =====================================================================
// Attention: CTA = 128q x 1 head, 8 warps, warp = 16q x 64keys x 64d.
// 2 CTAs/SM (regs < 128): 4 warps/SMSP for latency hiding + finer waves.
// fp16-acc S (packed = PV A-operand), ex2.f16x2, 3-stage bulk pipeline.
// smem bytes: K[s] @ s*8192 ; V[s] @ 24576 + s*8192 ; mbars @ 49152
// =====================================================================
#define AT_SMEM (49152 + 32)

__global__ __launch_bounds__(256, 2)
void attn_mma(float* __restrict__ out)
{
    extern __shared__ char smc[];
    const uint32_t sb = smem_u32(smc);
    const uint32_t mb0 = sb + 49152;
    const int tid = threadIdx.x;
    const int wid = tid >> 5, lane = tid & 31;
    const int gid = lane >> 2, tig = lane & 3;
    const int bh = blockIdx.y;
    const int s0 = blockIdx.x * 128;

    // ---- Q fragments in registers: 1 m-group (16q) x 4 k-steps ----
    uint4 qf[4];
    {
        const unsigned short* qb = g_q + ((size_t)bh * SSEQ + s0 + wid * 16) * DKK;
        #pragma unroll
        for (int ks = 0; ks < 4; ks++) {
            int c = 16 * ks + 2 * tig;
            qf[ks].x = *(const uint32_t*)(qb + gid * DKK + c);
            qf[ks].y = *(const uint32_t*)(qb + (gid + 8) * DKK + c);
            qf[ks].z = *(const uint32_t*)(qb + gid * DKK + c + 8);
            qf[ks].w = *(const uint32_t*)(qb + (gid + 8) * DKK + c + 8);
        }
    }

    const unsigned short* kg = g_k + (size_t)bh * 131072;
    const unsigned short* vg = g_v + (size_t)bh * 131072;

    auto issue = [&](int t, int b) {
        uint32_t mbar = mb0 + b * 8;
        MBAR_EXPECT(mbar, 16384u);
        BULK_G2S(sb + b * 8192,         (const void*)(kg + t * 4096), 8192u, mbar);
        BULK_G2S(sb + 24576 + b * 8192, (const void*)(vg + t * 4096), 8192u, mbar);
    };

    if (tid == 0) { MBAR_INIT(mb0, 1); MBAR_INIT(mb0 + 8, 1); MBAR_INIT(mb0 + 16, 1); }
    __syncthreads();
    if (tid == 0) { issue(0, 0); issue(1, 1); }

    float oacc[8][4];
    #pragma unroll
    for (int dn = 0; dn < 8; dn++)
        #pragma unroll
        for (int e = 0; e < 4; e++) oacc[dn][e] = 0.f;
    float lsum0 = 0.f, lsum1 = 0.f;

    int buf = 0, par = 0;
    #pragma unroll 1
    for (int t = 0; t < 32; t++) {
        MBAR_WAIT(mb0 + buf * 8, par);
        __syncthreads();
        if (t + 2 < 32 && tid == 0) {
            int nbuf = buf + 2; if (nbuf >= 3) nbuf -= 3;
            issue(t + 2, nbuf);
        }

        const uint4* Kp = (const uint4*)(smc + buf * 8192);
        const uint4* Vp = (const uint4*)(smc + 24576 + buf * 8192);

        // ---- S = Q @ K^T (fp16 accumulators, packed) ----
        uint32_t sacc[8][2];
        #pragma unroll
        for (int tn = 0; tn < 8; tn++) { sacc[tn][0] = 0u; sacc[tn][1] = 0u; }

        #pragma unroll
        for (int sp = 0; sp < 2; sp++) {
            #pragma unroll
            for (int tn = 0; tn < 8; tn++) {
                uint4 kb = Kp[(tn * 2 + sp) * 32 + lane];
                mma16h(sacc[tn], qf[2 * sp    ], kb.x, kb.y);
                mma16h(sacc[tn], qf[2 * sp + 1], kb.z, kb.w);
            }
        }

        // ---- P = ex2(S) in f16x2 (already PV A-operand layout); lsum exact ----
        #pragma unroll
        for (int tn = 0; tn < 8; tn++) {
            uint32_t plo = ex2h2(sacc[tn][0]);
            uint32_t phi = ex2h2(sacc[tn][1]);
            sacc[tn][0] = plo;
            sacc[tn][1] = phi;
            float2 f0 = __half22float2(*(const __half2*)&plo);
            float2 f1 = __half22float2(*(const __half2*)&phi);
            lsum0 += f0.x + f0.y;
            lsum1 += f1.x + f1.y;
        }

        // ---- O += P @ V ----
        #pragma unroll
        for (int kcp = 0; kcp < 2; kcp++) {
            #pragma unroll
            for (int dn = 0; dn < 8; dn++) {
                uint4 vb = Vp[(dn * 2 + kcp) * 32 + lane];
                mma16(oacc[dn],
                      sacc[4*kcp    ][0], sacc[4*kcp    ][1],
                      sacc[4*kcp + 1][0], sacc[4*kcp + 1][1],
                      vb.x, vb.y);
                mma16(oacc[dn],
                      sacc[4*kcp + 2][0], sacc[4*kcp + 2][1],
                      sacc[4*kcp + 3][0], sacc[4*kcp + 3][1],
                      vb.z, vb.w);
            }
        }
        if (++buf == 3) { buf = 0; par ^= 1; }
    }

    // ---- finalize l (quad reduce) and write out ----
    lsum0 += __shfl_xor_sync(0xffffffffu, lsum0, 1);
    lsum0 += __shfl_xor_sync(0xffffffffu, lsum0, 2);
    lsum1 += __shfl_xor_sync(0xffffffffu, lsum1, 1);
    lsum1 += __shfl_xor_sync(0xffffffffu, lsum1, 2);
    const float inv0 = 1.f / lsum0;
    const float inv1 = 1.f / lsum1;

    const int b = bh >> 4, h = bh & (HHEADS - 1);
    float* o0 = out + ((size_t)b * SSEQ + s0 + wid * 16 + gid) * EEMB + h * DKK;
    float* o1 = o0 + 8 * EEMB;
    #pragma unroll
    for (int dn = 0; dn < 8; dn++) {
        int c = dn * 8 + 2 * tig;
        *(float2*)(o0 + c) = make_float2(oacc[dn][0] * inv0, oacc[dn][1] * inv0);
        *(float2*)(o1 + c) = make_float2(oacc[dn][2] * inv1, oacc[dn][3] * inv1);
    }
}

// ===================== launch =====================
extern "C" void kernel_launch(void* const* d_in, const int* in_sizes, int n_in,
                              void* d_out, int out_size)
{
    const float* x     = (const float*)d_in[0];
    const float* Wk    = (const float*)d_in[1];
    const float* Wv    = (const float*)d_in[2];
    const float* Wq    = (const float*)d_in[3];
    const float* theta = (const float*)d_in[4];
    float* out = (float*)d_out;

    cudaFuncSetAttribute(proj_mma, cudaFuncAttributeMaxDynamicSharedMemorySize, PJ_SMEM);
    cudaFuncSetAttribute(attn_mma, cudaFuncAttributeMaxDynamicSharedMemorySize, AT_SMEM);

    prep_kernel<<<dim3(2048, 4), 256>>>(x, Wk, Wv, Wq);

    dim3 gp(3 * EEMB / 128, (BBATCH * SSEQ) / 128);   // (24, 32)
    proj_mma<<<gp, 256, PJ_SMEM>>>(theta);

    dim3 ga(SSEQ / 128, BBATCH * HHEADS);              // (16, 32)
    attn_mma<<<ga, 256, AT_SMEM>>>(out);
}

// round 17
// speedup vs baseline: 1.0933x; 1.0933x over previous
#include <cuda_runtime.h>
#include <cuda_fp16.h>
#include <math.h>
#include <stdint.h>

#define BBATCH 2
#define SSEQ 2048
#define EEMB 1024
#define HHEADS 16
#define DKK 64
#define BHS (BBATCH*HHEADS*SSEQ)

// Scratch (all fp16, fragment-interleaved for single-LDS.128 operand fetch)
__device__ unsigned short g_xi[4096*1024];
__device__ unsigned short g_wi[3][1024*1024];
__device__ unsigned short g_k[BHS*DKK];
__device__ unsigned short g_v[BHS*DKK];
__device__ unsigned short g_q[BHS*DKK];
__device__ int g_cnt[48];   // [mode][nb][b] completion counters (target 16)

// ---------------- helpers ----------------
__device__ __forceinline__ void mma16(float* d, uint32_t a0, uint32_t a1,
                                      uint32_t a2, uint32_t a3,
                                      uint32_t b0, uint32_t b1)
{
    asm volatile("mma.sync.aligned.m16n8k16.row.col.f32.f16.f16.f32 "
        "{%0,%1,%2,%3}, {%4,%5,%6,%7}, {%8,%9}, {%0,%1,%2,%3};"
        : "+f"(d[0]), "+f"(d[1]), "+f"(d[2]), "+f"(d[3])
        : "r"(a0), "r"(a1), "r"(a2), "r"(a3), "r"(b0), "r"(b1));
}
__device__ __forceinline__ void mma16v(float* d, const uint4& a, uint32_t b0, uint32_t b1){
    mma16(d, a.x, a.y, a.z, a.w, b0, b1);
}
__device__ __forceinline__ void mma16h(uint32_t* d, const uint4& a, uint32_t b0, uint32_t b1)
{
    asm volatile("mma.sync.aligned.m16n8k16.row.col.f16.f16.f16.f16 "
        "{%0,%1}, {%2,%3,%4,%5}, {%6,%7}, {%0,%1};"
        : "+r"(d[0]), "+r"(d[1])
        : "r"(a.x), "r"(a.y), "r"(a.z), "r"(a.w), "r"(b0), "r"(b1));
}
__device__ __forceinline__ uint32_t ex2h2(uint32_t x){
    uint32_t r; asm("ex2.approx.f16x2 %0, %1;" : "=r"(r) : "r"(x)); return r;
}
__device__ __forceinline__ uint32_t packh2(float a, float b){
    __half2 h = __floats2half2_rn(a, b);
    return *(uint32_t*)&h;
}
__device__ __forceinline__ uint32_t smem_u32(const void* p){
    uint32_t a;
    asm("{ .reg .u64 t; cvta.to.shared.u64 t, %1; cvt.u32.u64 %0, t; }" : "=r"(a) : "l"(p));
    return a;
}

#define MBAR_INIT(a, c) asm volatile("mbarrier.init.shared.b64 [%0], %1;" :: "r"(a), "r"(c) : "memory")
#define MBAR_EXPECT(a, bytes) \
    asm volatile("mbarrier.arrive.expect_tx.shared.b64 _, [%0], %1;" :: "r"(a), "r"(bytes) : "memory")
#define BULK_G2S(dst, src, bytes, mbar) \
    asm volatile("cp.async.bulk.shared::cta.global.mbarrier::complete_tx::bytes [%0], [%1], %2, [%3];" \
        :: "r"(dst), "l"(src), "r"(bytes), "r"(mbar) : "memory")

#define MBAR_WAIT(mbar, par) do {                                            \
    uint32_t _m = (mbar); uint32_t _p = (par); uint32_t _done;               \
    asm volatile("{ .reg .pred p; mbarrier.try_wait.parity.acquire.cta.shared::cta.b64 p, [%1], %2; selp.b32 %0,1,0,p; }" \
        : "=r"(_done) : "r"(_m), "r"(_p) : "memory");                        \
    if (!_done) {                                                            \
        asm volatile("{ .reg .pred P1; WL%=: mbarrier.try_wait.parity.acquire.cta.shared::cta.b64 P1, [%0], %1, 0x989680; @P1 bra.uni WD%=; bra.uni WL%=; WD%=: }" \
            :: "r"(_m), "r"(_p) : "memory");                                 \
    }                                                                        \
} while(0)

// =====================================================================
// Prep (DEST-MAJOR, unchanged) + counter reset
// =====================================================================
__global__ __launch_bounds__(256)
void prep_kernel(const float* __restrict__ x, const float* __restrict__ Wk,
                 const float* __restrict__ Wv, const float* __restrict__ Wq)
{
    const int t = blockIdx.x * 256 + threadIdx.x;
    if (blockIdx.y == 0) {
        int l5 = t & 31, gid = l5 >> 2, tig = l5 & 3;
        int blk = t >> 5;
        int g = (blk & 31) >> 2, ks = blk & 3;
        int rbch = blk >> 5, ch = rbch & 15, rb = rbch >> 4;
        int mb = rb * 128 + g * 16 + gid;
        int kb = ch * 64 + ks * 16 + tig * 2;
        const float* xr0 = x + (size_t)mb * EEMB + kb;
        const float* xr8 = xr0 + 8 * EEMB;
        float2 a0 = *(const float2*)(xr0);
        float2 a1 = *(const float2*)(xr8);
        float2 a2 = *(const float2*)(xr0 + 8);
        float2 a3 = *(const float2*)(xr8 + 8);
        uint4 w;
        w.x = packh2(a0.x, a0.y);
        w.y = packh2(a1.x, a1.y);
        w.z = packh2(a2.x, a2.y);
        w.w = packh2(a3.x, a3.y);
        *(uint4*)((uint32_t*)g_xi + (size_t)t * 4) = w;
    } else {
        if (blockIdx.x == 0 && blockIdx.y == 1 && threadIdx.x < 48)
            g_cnt[threadIdx.x] = 0;
        if (t >= 131072) return;
        const float* W = (blockIdx.y == 1) ? Wk : (blockIdx.y == 2) ? Wv : Wq;
        unsigned short* dst = g_wi[blockIdx.y - 1];
        int l5 = t & 31, gid = l5 >> 2, tig = l5 & 3;
        int blk = t >> 5;
        int ng = (blk & 31) >> 1, sp = blk & 1;
        int nbch = blk >> 5, ch = nbch & 15, nb = nbch >> 4;
        int n = nb * 128 + ng * 8 + gid;
        int kbase = ch * 64 + sp * 32 + tig * 2;
        const float* wr = W + (size_t)n * EEMB + kbase;
        float2 b0 = *(const float2*)(wr);
        float2 b1 = *(const float2*)(wr + 8);
        float2 b2 = *(const float2*)(wr + 16);
        float2 b3 = *(const float2*)(wr + 24);
        uint4 w;
        w.x = packh2(b0.x, b0.y);
        w.y = packh2(b1.x, b1.y);
        w.z = packh2(b2.x, b2.y);
        w.w = packh2(b3.x, b3.y);
        *(uint4*)((uint32_t*)dst + (size_t)t * 4) = w;
    }
}

// =====================================================================
// Fused kernel: bids 0..767 = proj units; 768..1279 = attn units (128q).
// Per-head readiness via g_cnt; smem 96KB, 2 CTAs/SM.
// Proj smem: A[s] @ s*16384 ; W[s] @ 49152 + s*16384
// Attn smem: K[s] @ s*8192  ; V[s] @ 24576 + s*8192
// mbars @ byte 98304 (3 x 8B)
// =====================================================================
#define FU_SMEM (98304 + 32)

__global__ __launch_bounds__(256, 2)
void fused_mma(const float* __restrict__ theta, float* __restrict__ out)
{
    extern __shared__ char smc[];
    const uint32_t sb = smem_u32(smc);
    const uint32_t mb0 = sb + 98304;
    const int tid = threadIdx.x;
    const int wid = tid >> 5, lane = tid & 31;
    const int gid = lane >> 2, tig = lane & 3;
    const int bid = blockIdx.x;

    if (tid == 0) { MBAR_INIT(mb0, 1); MBAR_INIT(mb0 + 8, 1); MBAR_INIT(mb0 + 16, 1); }
    __syncthreads();

    if (bid < 768) {
        // ================= PROJ unit =================
        const int xu = bid % 24, yu = bid / 24;
        const int wm = wid >> 1, wn = wid & 1;
        const int row0 = yu * 128;
        const int mode = xu >> 3;
        const int nb = xu & 7;
        const int coll = nb * 128;

        float acc[2][8][4];
        #pragma unroll
        for (int i = 0; i < 2; i++)
            #pragma unroll
            for (int j = 0; j < 8; j++)
                #pragma unroll
                for (int e = 0; e < 4; e++) acc[i][j][e] = 0.f;

        const unsigned short* Ab = g_xi + (size_t)yu * 131072;
        const unsigned short* Wb = g_wi[mode] + (size_t)nb * 131072;

        auto issue = [&](int ch, int b) {
            uint32_t mbar = mb0 + b * 8;
            MBAR_EXPECT(mbar, 32768u);
            BULK_G2S(sb + b * 16384,         (const void*)(Ab + ch * 8192), 16384u, mbar);
            BULK_G2S(sb + 49152 + b * 16384, (const void*)(Wb + ch * 8192), 16384u, mbar);
        };

        if (tid == 0) { issue(0, 0); issue(1, 1); }

        int buf = 0, par = 0;
        #pragma unroll 1
        for (int ch = 0; ch < 16; ch++) {
            MBAR_WAIT(mb0 + buf * 8, par);
            __syncthreads();
            if (ch + 2 < 16 && tid == 0) {
                int nbuf = buf + 2; if (nbuf >= 3) nbuf -= 3;
                issue(ch + 2, nbuf);
            }

            const uint4* As = (const uint4*)(smc + buf * 16384);
            const uint4* Ws = (const uint4*)(smc + 49152 + buf * 16384);
            #pragma unroll
            for (int sp = 0; sp < 2; sp++) {
                uint4 af[2][2];
                #pragma unroll
                for (int tm = 0; tm < 2; tm++)
                    #pragma unroll
                    for (int kso = 0; kso < 2; kso++)
                        af[tm][kso] = As[((2*wm+tm)*4 + 2*sp+kso) * 32 + lane];
                #pragma unroll
                for (int tn = 0; tn < 8; tn++) {
                    uint4 wb = Ws[((wn*8+tn)*2 + sp) * 32 + lane];
                    #pragma unroll
                    for (int tm = 0; tm < 2; tm++) {
                        mma16v(acc[tm][tn], af[tm][0], wb.x, wb.y);
                        mma16v(acc[tm][tn], af[tm][1], wb.z, wb.w);
                    }
                }
            }
            if (++buf == 3) { buf = 0; par ^= 1; }
        }

        // epilogue
        #pragma unroll
        for (int tm = 0; tm < 2; tm++) {
            #pragma unroll
            for (int tn = 0; tn < 8; tn++) {
                #pragma unroll
                for (int half = 0; half < 2; half++) {
                    int m = row0 + wm * 32 + tm * 16 + gid + half * 8;
                    int nn = coll + wn * 64 + tn * 8 + 2 * tig;
                    int b = m >> 11, s = m & (SSEQ - 1);
                    int h = nn >> 6, d = nn & (DKK - 1);
                    int bh = b * HHEADS + h;
                    float v0 = acc[tm][tn][2 * half];
                    float v1 = acc[tm][tn][2 * half + 1];
                    if (mode == 0) {
                        int tile = s >> 6, key = s & 63;
                        int ng = key >> 3, gidk = key & 7;
                        int ks = d >> 4, sp = ks >> 1, kso = ks & 1;
                        int k16 = d & 15, khalf = k16 >> 3, tigk = (k16 & 7) >> 1;
                        int word = ((ng * 2 + sp) * 32 + gidk * 4 + tigk) * 4 + (kso * 2 + khalf);
                        ((uint32_t*)g_k)[(size_t)(bh * 32 + tile) * 2048 + word] = packh2(v0, v1);
                    } else if (mode == 1) {
                        float pv0 = __shfl_xor_sync(0xffffffffu, v0, 4);
                        float pv1 = __shfl_xor_sync(0xffffffffu, v1, 4);
                        if (!(gid & 1)) {
                            int tile = s >> 6, key = s & 63;
                            int kc = key >> 4, kcp = kc >> 1, kco = kc & 1;
                            int key16 = key & 15, khalf = key16 >> 3, tigv = (key16 & 7) >> 1;
                            size_t base = (size_t)(bh * 32 + tile) * 2048;
                            int dn0 = d >> 3, gid0 = d & 7;
                            int w0 = ((dn0 * 2 + kcp) * 32 + gid0 * 4 + tigv) * 4 + (kco * 2 + khalf);
                            int d1 = d + 1, dn1 = d1 >> 3, gid1 = d1 & 7;
                            int w1 = ((dn1 * 2 + kcp) * 32 + gid1 * 4 + tigv) * 4 + (kco * 2 + khalf);
                            ((uint32_t*)g_v)[base + w0] = packh2(v0, pv0);
                            ((uint32_t*)g_v)[base + w1] = packh2(v1, pv1);
                        }
                    } else {
                        float q0 = __cosf(v0 + __ldg(&theta[d]))     * 0.18033688011112042f;
                        float q1 = __cosf(v1 + __ldg(&theta[d + 1])) * 0.18033688011112042f;
                        ((uint32_t*)g_q)[(((size_t)bh * SSEQ + s) * DKK + d) >> 1] = packh2(q0, q1);
                    }
                }
            }
        }
        // signal completion: (mode, nb, b = yu>>4)
        __threadfence();
        __syncthreads();
        if (tid == 0) atomicAdd(&g_cnt[mode * 16 + nb * 2 + (yu >> 4)], 1);
        return;
    }

    // ================= ATTN unit (128q) =================
    const int v = bid - 768;
    const int bh = v >> 4;
    const int s0 = (v & 15) * 128;
    const int b = bh >> 4, h = bh & (HHEADS - 1);

    // spin until this head's K, V, Q projections are complete
    if (tid == 0) {
        volatile int* c = g_cnt;
        int idx = (h >> 1) * 2 + b;
        while (c[idx] < 16 || c[16 + idx] < 16 || c[32 + idx] < 16)
            __nanosleep(200);
    }
    __syncthreads();
    __threadfence();

    uint4 qf[4];
    {
        const unsigned short* qb = g_q + ((size_t)bh * SSEQ + s0 + wid * 16) * DKK;
        #pragma unroll
        for (int ks = 0; ks < 4; ks++) {
            int c = 16 * ks + 2 * tig;
            qf[ks].x = *(const uint32_t*)(qb + gid * DKK + c);
            qf[ks].y = *(const uint32_t*)(qb + (gid + 8) * DKK + c);
            qf[ks].z = *(const uint32_t*)(qb + gid * DKK + c + 8);
            qf[ks].w = *(const uint32_t*)(qb + (gid + 8) * DKK + c + 8);
        }
    }

    const unsigned short* kg = g_k + (size_t)bh * 131072;
    const unsigned short* vg = g_v + (size_t)bh * 131072;

    auto issue = [&](int t, int bu) {
        uint32_t mbar = mb0 + bu * 8;
        MBAR_EXPECT(mbar, 16384u);
        BULK_G2S(sb + bu * 8192,         (const void*)(kg + t * 4096), 8192u, mbar);
        BULK_G2S(sb + 24576 + bu * 8192, (const void*)(vg + t * 4096), 8192u, mbar);
    };

    if (tid == 0) { issue(0, 0); issue(1, 1); }

    float oacc[8][4];
    #pragma unroll
    for (int dn = 0; dn < 8; dn++)
        #pragma unroll
        for (int e = 0; e < 4; e++) oacc[dn][e] = 0.f;
    float lsum0 = 0.f, lsum1 = 0.f;

    int buf = 0, par = 0;
    #pragma unroll 1
    for (int t = 0; t < 32; t++) {
        MBAR_WAIT(mb0 + buf * 8, par);
        __syncthreads();
        if (t + 2 < 32 && tid == 0) {
            int nbuf = buf + 2; if (nbuf >= 3) nbuf -= 3;
            issue(t + 2, nbuf);
        }

        const uint4* Kp = (const uint4*)(smc + buf * 8192);
        const uint4* Vp = (const uint4*)(smc + 24576 + buf * 8192);

        uint32_t sacc[8][2];
        #pragma unroll
        for (int tn = 0; tn < 8; tn++) { sacc[tn][0] = 0u; sacc[tn][1] = 0u; }

        #pragma unroll
        for (int sp = 0; sp < 2; sp++) {
            #pragma unroll
            for (int tn = 0; tn < 8; tn++) {
                uint4 kb = Kp[(tn * 2 + sp) * 32 + lane];
                mma16h(sacc[tn], qf[2 * sp    ], kb.x, kb.y);
                mma16h(sacc[tn], qf[2 * sp + 1], kb.z, kb.w);
            }
        }

        #pragma unroll
        for (int tn = 0; tn < 8; tn++) {
            uint32_t plo = ex2h2(sacc[tn][0]);
            uint32_t phi = ex2h2(sacc[tn][1]);
            sacc[tn][0] = plo;
            sacc[tn][1] = phi;
            float2 f0 = __half22float2(*(const __half2*)&plo);
            float2 f1 = __half22float2(*(const __half2*)&phi);
            lsum0 += f0.x + f0.y;
            lsum1 += f1.x + f1.y;
        }

        #pragma unroll
        for (int kcp = 0; kcp < 2; kcp++) {
            #pragma unroll
            for (int dn = 0; dn < 8; dn++) {
                uint4 vb = Vp[(dn * 2 + kcp) * 32 + lane];
                mma16(oacc[dn],
                      sacc[4*kcp    ][0], sacc[4*kcp    ][1],
                      sacc[4*kcp + 1][0], sacc[4*kcp + 1][1],
                      vb.x, vb.y);
                mma16(oacc[dn],
                      sacc[4*kcp + 2][0], sacc[4*kcp + 2][1],
                      sacc[4*kcp + 3][0], sacc[4*kcp + 3][1],
                      vb.z, vb.w);
            }
        }
        if (++buf == 3) { buf = 0; par ^= 1; }
    }

    lsum0 += __shfl_xor_sync(0xffffffffu, lsum0, 1);
    lsum0 += __shfl_xor_sync(0xffffffffu, lsum0, 2);
    lsum1 += __shfl_xor_sync(0xffffffffu, lsum1, 1);
    lsum1 += __shfl_xor_sync(0xffffffffu, lsum1, 2);
    const float inv0 = 1.f / lsum0;
    const float inv1 = 1.f / lsum1;

    float* o0 = out + ((size_t)b * SSEQ + s0 + wid * 16 + gid) * EEMB + h * DKK;
    float* o1 = o0 + 8 * EEMB;
    #pragma unroll
    for (int dn = 0; dn < 8; dn++) {
        int c = dn * 8 + 2 * tig;
        *(float2*)(o0 + c) = make_float2(oacc[dn][0] * inv0, oacc[dn][1] * inv0);
        *(float2*)(o1 + c) = make_float2(oacc[dn][2] * inv1, oacc[dn][3] * inv1);
    }
}

// ===================== launch =====================
extern "C" void kernel_launch(void* const* d_in, const int* in_sizes, int n_in,
                              void* d_out, int out_size)
{
    const float* x     = (const float*)d_in[0];
    const float* Wk    = (const float*)d_in[1];
    const float* Wv    = (const float*)d_in[2];
    const float* Wq    = (const float*)d_in[3];
    const float* theta = (const float*)d_in[4];
    float* out = (float*)d_out;

    cudaFuncSetAttribute(fused_mma, cudaFuncAttributeMaxDynamicSharedMemorySize, FU_SMEM);

    prep_kernel<<<dim3(2048, 4), 256>>>(x, Wk, Wv, Wq);
    fused_mma<<<1280, 256, FU_SMEM>>>(theta, out);
}